// round 5
// baseline (speedup 1.0000x reference)
#include <cuda_runtime.h>
#include <cuda_bf16.h>
#include <cstdint>

// CRF mean NLL — 4 warps/CTA, one per SMSP, each warp fully autonomous.
// emissions (16384,512,5) f32; transitions (5,5); start/end (5,); tags (16384,512) i32; mask all-ones.
//
// Insight from R4: SMSP = wid%4 -> 1-warp CTAs stacked all warps on SMSP0 (MUFU rt=8
// serialization). Now TPB=128/GRID=128 puts one warp on each SMSP. Each warp owns
// 32 sequences + its own SMEM partition + its own cp.async pipeline (NBUF=4, PDIST=3).
// No __syncthreads in the main loop.

#define TPB         128
#define NWARP       4
#define GRID        128
#define CHUNK       8
#define L_SEQ       512
#define NCHUNK      (L_SEQ / CHUNK)      // 64
#define SEQ_PER_W   32
#define DATA_F4     10                   // CHUNK*5 floats = 10 float4 per seq per chunk
#define ROW_F4      11                   // padded -> conflict-free LDS.128
#define TAG_F4      2                    // CHUNK tags = 2 int4
#define TROW_F4     3                    // padded -> conflict-free
#define NBUF        4
#define PDIST       3
#define EM_ROW_GF4  (L_SEQ * 5 / 4)      // 640 float4 per sequence
#define TG_ROW_GI4  (L_SEQ / 4)          // 128 int4 per sequence

// dynamic smem layout (float4 units):
//   em: NWARP * NBUF * SEQ_PER_W * ROW_F4  = 4*4*32*11 = 5632 f4  (90112 B)
//   tg: NWARP * NBUF * SEQ_PER_W * TROW_F4 = 4*4*32*3  = 1536 i4  (24576 B)
#define EM_W_F4     (NBUF * SEQ_PER_W * ROW_F4)    // 1408 f4 per warp
#define TG_W_I4     (NBUF * SEQ_PER_W * TROW_F4)   // 384 i4 per warp
#define EM_TOT_F4   (NWARP * EM_W_F4)              // 5632
#define EMBUF_B     (SEQ_PER_W * ROW_F4 * 16)      // 5632 B per buffer
#define TGBUF_B     (SEQ_PER_W * TROW_F4 * 16)     // 1536 B per buffer
#define DYN_BYTES   ((EM_TOT_F4 + NWARP * TG_W_I4) * 16)   // 114688

__device__ float        g_partial[GRID];
__device__ unsigned int g_ticket = 0;

__device__ __forceinline__ void cp_async16(uint32_t saddr, const void* gptr) {
    asm volatile("cp.async.cg.shared.global [%0], [%1], 16;\n" :: "r"(saddr), "l"(gptr));
}
__device__ __forceinline__ void cp_commit() {
    asm volatile("cp.async.commit_group;\n");
}
__device__ __forceinline__ void cp_waitP() {
    asm volatile("cp.async.wait_group 3;\n");   // issue-first: PDIST+1 pending -> retire chunk c
}

__global__ __launch_bounds__(TPB)
void crf_nll_kernel(const float* __restrict__ em,
                    const float* __restrict__ trans,
                    const float* __restrict__ startT,
                    const float* __restrict__ endT,
                    const int*   __restrict__ tags,
                    float* __restrict__ out)
{
    extern __shared__ float4 dyn[];
    __shared__ float s_T[25], s_start[5], s_end[5];
    __shared__ float s_red[NWARP];
    __shared__ unsigned s_tk;

    const int tid  = threadIdx.x;
    const int wid  = tid >> 5;
    const int lane = tid & 31;

    if (tid < 25) s_T[tid] = trans[tid];
    if (tid < 5)  { s_start[tid] = startT[tid]; s_end[tid] = endT[tid]; }
    __syncthreads();     // tables ready (once; main loop is barrier-free)

    float E[25];
#pragma unroll
    for (int i = 0; i < 25; ++i) E[i] = __expf(__ldg(&trans[i]));

    // per-warp SMEM partitions
    float4* emBase = dyn + wid * EM_W_F4;
    int4*   tgBase = reinterpret_cast<int4*>(dyn + EM_TOT_F4) + wid * TG_W_I4;

    const long seq0 = (long)blockIdx.x * TPB + wid * SEQ_PER_W;

    const float4* gem = reinterpret_cast<const float4*>(em);
    const int4*   gtg = reinterpret_cast<const int4*>(tags);

    const float4* esrc[DATA_F4];  uint32_t edst[DATA_F4];
#pragma unroll
    for (int k = 0; k < DATA_F4; ++k) {
        int idx = lane + 32 * k;               // 0..319
        int sq  = idx / DATA_F4;
        int v   = idx - sq * DATA_F4;
        esrc[k] = gem + (seq0 + sq) * EM_ROW_GF4 + v;
        edst[k] = (uint32_t)__cvta_generic_to_shared(&emBase[sq * ROW_F4 + v]);
    }
    const int4* tsrc[TAG_F4];  uint32_t tdst[TAG_F4];
#pragma unroll
    for (int k = 0; k < TAG_F4; ++k) {
        int idx = lane + 32 * k;               // 0..63
        int sq  = idx >> 1;
        int v   = idx & 1;
        tsrc[k] = gtg + (seq0 + sq) * TG_ROW_GI4 + v;
        tdst[k] = (uint32_t)__cvta_generic_to_shared(&tgBase[sq * TROW_F4 + v]);
    }

    // ---- prologue: issue chunks 0..2 ----
#pragma unroll
    for (int c = 0; c < PDIST; ++c) {
#pragma unroll
        for (int k = 0; k < DATA_F4; ++k)
            cp_async16(edst[k] + (uint32_t)c * EMBUF_B, esrc[k] + c * DATA_F4);
#pragma unroll
        for (int k = 0; k < TAG_F4; ++k)
            cp_async16(tdst[k] + (uint32_t)c * TGBUF_B, tsrc[k] + c * TAG_F4);
        cp_commit();
    }

    float w0 = 0.f, w1 = 0.f, w2 = 0.f, w3 = 0.f, w4 = 0.f;
    float clog = 0.f, num = 0.f;
    int prev = 0;

#pragma unroll 1
    for (int c = 0; c < NCHUNK; ++c) {
        const int buf = c & (NBUF - 1);

        // issue chunk c+PDIST first (overlaps the wait); commit ALWAYS (uniform count)
        {
            const int pc = c + PDIST;
            if (pc < NCHUNK) {
                const uint32_t pb = (uint32_t)(pc & (NBUF - 1));
#pragma unroll
                for (int k = 0; k < DATA_F4; ++k)
                    cp_async16(edst[k] + pb * EMBUF_B, esrc[k] + pc * DATA_F4);
#pragma unroll
                for (int k = 0; k < TAG_F4; ++k)
                    cp_async16(tdst[k] + pb * TGBUF_B, tsrc[k] + pc * TAG_F4);
            }
            cp_commit();
        }

        cp_waitP();        // chunk c's group retired
        __syncwarp();      // all lanes' copies visible (warp-local)

        float m[CHUNK * 5];
        {
            const float4* rowp = &emBase[(buf * SEQ_PER_W + lane) * ROW_F4];
#pragma unroll
            for (int v = 0; v < DATA_F4; ++v) {
                float4 q = rowp[v];
                m[4*v+0] = q.x; m[4*v+1] = q.y; m[4*v+2] = q.z; m[4*v+3] = q.w;
            }
        }
        int tg8[8];
        {
            const int4* trow = &tgBase[(buf * SEQ_PER_W + lane) * TROW_F4];
            int4 ta = trow[0], tb = trow[1];
            tg8[0]=ta.x; tg8[1]=ta.y; tg8[2]=ta.z; tg8[3]=ta.w;
            tg8[4]=tb.x; tg8[5]=tb.y; tg8[6]=tb.z; tg8[7]=tb.w;
        }

#pragma unroll
        for (int t = 0; t < CHUNK; ++t) {
            const float m0 = m[t*5+0], m1 = m[t*5+1], m2 = m[t*5+2],
                        m3 = m[t*5+3], m4 = m[t*5+4];
            const int tg = tg8[t];

            float es = m0;
            es = (tg == 1) ? m1 : es;
            es = (tg == 2) ? m2 : es;
            es = (tg == 3) ? m3 : es;
            es = (tg == 4) ? m4 : es;

            if (t == 0 && c == 0) {
                w0 = __expf(s_start[0] + m0);
                w1 = __expf(s_start[1] + m1);
                w2 = __expf(s_start[2] + m2);
                w3 = __expf(s_start[3] + m3);
                w4 = __expf(s_start[4] + m4);
                num = s_start[tg] + es;
            } else {
                const float e0 = __expf(m0), e1 = __expf(m1), e2 = __expf(m2),
                            e3 = __expf(m3), e4 = __expf(m4);
                const float a0 = fmaf(w4, E[20], fmaf(w3, E[15], fmaf(w2, E[10], fmaf(w1, E[5],  w0 * E[0]))));
                const float a1 = fmaf(w4, E[21], fmaf(w3, E[16], fmaf(w2, E[11], fmaf(w1, E[6],  w0 * E[1]))));
                const float a2 = fmaf(w4, E[22], fmaf(w3, E[17], fmaf(w2, E[12], fmaf(w1, E[7],  w0 * E[2]))));
                const float a3 = fmaf(w4, E[23], fmaf(w3, E[18], fmaf(w2, E[13], fmaf(w1, E[8],  w0 * E[3]))));
                const float a4 = fmaf(w4, E[24], fmaf(w3, E[19], fmaf(w2, E[14], fmaf(w1, E[9],  w0 * E[4]))));
                w0 = e0 * a0; w1 = e1 * a1; w2 = e2 * a2; w3 = e3 * a3; w4 = e4 * a4;
                num += s_T[prev * 5 + tg] + es;
            }
            prev = tg;
        }

        // renormalize every 8 steps (growth bound 8*(max|em|+1.8) < 88 -> no overflow)
        const float mx  = fmaxf(fmaxf(w0, w1), fmaxf(fmaxf(w2, w3), w4));
        clog += __logf(mx);
        const float inv = __fdividef(1.0f, mx);
        w0 *= inv; w1 *= inv; w2 *= inv; w3 *= inv; w4 *= inv;
    }

    // ---- epilogue: log partition + gold end transition ----
    const float sden = fmaf(w4, __expf(s_end[4]),
                       fmaf(w3, __expf(s_end[3]),
                       fmaf(w2, __expf(s_end[2]),
                       fmaf(w1, __expf(s_end[1]), w0 * __expf(s_end[0])))));
    const float den = clog + __logf(sden);
    num += s_end[prev];

    float val = den - num;

    // ---- warp reduce -> block reduce -> last-CTA grid reduce ----
#pragma unroll
    for (int off = 16; off > 0; off >>= 1)
        val += __shfl_down_sync(0xffffffffu, val, off);
    if (lane == 0) s_red[wid] = val;
    __syncthreads();

    if (tid == 0) {
        g_partial[blockIdx.x] = s_red[0] + s_red[1] + s_red[2] + s_red[3];
        __threadfence();
        s_tk = atomicInc(&g_ticket, GRID - 1);    // wraps to 0 -> replay-safe
    }
    __syncthreads();

    if (s_tk == GRID - 1 && wid == 0) {           // last CTA: warp 0 reduces partials
        __threadfence();
        float s = 0.0f;
#pragma unroll
        for (int i = lane; i < GRID; i += 32) {
            float p;
            asm volatile("ld.global.cv.f32 %0, [%1];" : "=f"(p) : "l"(g_partial + i));
            s += p;
        }
#pragma unroll
        for (int off = 16; off > 0; off >>= 1)
            s += __shfl_down_sync(0xffffffffu, s, off);
        if (lane == 0) out[0] = s * (1.0f / 16384.0f);
    }
}

extern "C" void kernel_launch(void* const* d_in, const int* in_sizes, int n_in,
                              void* d_out, int out_size)
{
    const float* em     = (const float*)d_in[0];
    const float* trans  = (const float*)d_in[1];
    const float* startT = (const float*)d_in[2];
    const float* endT   = (const float*)d_in[3];
    const int*   tags   = (const int*)  d_in[4];
    // d_in[5] = mask (all ones) -> ignored
    float* out = (float*)d_out;

    cudaFuncSetAttribute(crf_nll_kernel,
                         cudaFuncAttributeMaxDynamicSharedMemorySize, DYN_BYTES);
    crf_nll_kernel<<<GRID, TPB, DYN_BYTES>>>(em, trans, startT, endT, tags, out);
}

// round 6
// speedup vs baseline: 1.1468x; 1.1468x over previous
#include <cuda_runtime.h>
#include <cuda_bf16.h>
#include <cstdint>

// CRF mean NLL — R3 shell + ILP restructure:
//  - all 40 exps per chunk hoisted out of the serial step loop (independent MUFU burst)
//  - gold-emission gather via 1 LDS.32 from the SMEM tile (replaces 8-instr select tree)
//  - chunk-0 init uses precomputed exp(start): w_j = ES_j * e_j (no special-case exps)
// emissions (16384,512,5) f32; transitions (5,5); start/end (5,); tags (16384,512) i32; mask all-ones.

#define TPB         32
#define CHUNK       8
#define L_SEQ       512
#define NCHUNK      (L_SEQ / CHUNK)      // 64
#define GRID        512
#define SEQ_PER_CTA 32
#define DATA_F4     10                   // CHUNK*5 floats = 10 float4 per seq per chunk
#define ROW_F4      11                   // padded -> conflict-free LDS.128
#define TAG_F4      2
#define TROW_F4     3
#define NBUF        4
#define EM_ROW_GF4  (L_SEQ * 5 / 4)      // 640 float4 per sequence
#define TG_ROW_GI4  (L_SEQ / 4)          // 128 int4 per sequence

__device__ float        g_partial[GRID];
__device__ unsigned int g_ticket = 0;

__device__ __forceinline__ void cp_async16(uint32_t saddr, const void* gptr) {
    asm volatile("cp.async.cg.shared.global [%0], [%1], 16;\n" :: "r"(saddr), "l"(gptr));
}
__device__ __forceinline__ void cp_commit() {
    asm volatile("cp.async.commit_group;\n");
}
__device__ __forceinline__ void cp_wait2() {
    asm volatile("cp.async.wait_group 2;\n");
}

__global__ __launch_bounds__(TPB)
void crf_nll_kernel(const float* __restrict__ em,
                    const float* __restrict__ trans,
                    const float* __restrict__ startT,
                    const float* __restrict__ endT,
                    const int*   __restrict__ tags,
                    float* __restrict__ out)
{
    __shared__ float4 s_em[NBUF][SEQ_PER_CTA * ROW_F4];   // 22528 B
    __shared__ int4   s_tg[NBUF][SEQ_PER_CTA * TROW_F4];  //  6144 B
    __shared__ float  s_T[25], s_start[5];

    const int  lane = threadIdx.x;
    const long seq0 = (long)blockIdx.x * SEQ_PER_CTA;

    if (lane < 25) s_T[lane] = trans[lane];
    if (lane < 5)  s_start[lane] = startT[lane];
    __syncwarp();

    // E = exp(T), ES = exp(start) in registers (broadcast loads)
    float E[25];
#pragma unroll
    for (int i = 0; i < 25; ++i) E[i] = __expf(__ldg(&trans[i]));
    float ES[5];
#pragma unroll
    for (int i = 0; i < 5; ++i) ES[i] = __expf(__ldg(&startT[i]));

    // ---- per-lane copy addressing ----
    const float4* gem = reinterpret_cast<const float4*>(em);
    const int4*   gtg = reinterpret_cast<const int4*>(tags);

    const float4* esrc[DATA_F4];  uint32_t edst[DATA_F4];
#pragma unroll
    for (int k = 0; k < DATA_F4; ++k) {
        int idx = lane + 32 * k;
        int sq  = idx / DATA_F4;
        int v   = idx - sq * DATA_F4;
        esrc[k] = gem + (seq0 + sq) * EM_ROW_GF4 + v;
        edst[k] = (uint32_t)__cvta_generic_to_shared(&s_em[0][sq * ROW_F4 + v]);
    }
    const int4* tsrc[TAG_F4];  uint32_t tdst[TAG_F4];
#pragma unroll
    for (int k = 0; k < TAG_F4; ++k) {
        int idx = lane + 32 * k;
        int sq  = idx >> 1;
        int v   = idx & 1;
        tsrc[k] = gtg + (seq0 + sq) * TG_ROW_GI4 + v;
        tdst[k] = (uint32_t)__cvta_generic_to_shared(&s_tg[0][sq * TROW_F4 + v]);
    }

    const uint32_t EMBUF = (uint32_t)sizeof(s_em[0]);
    const uint32_t TGBUF = (uint32_t)sizeof(s_tg[0]);

    // ---- prologue: issue chunks 0..2 ----
#pragma unroll
    for (int c = 0; c < 3; ++c) {
#pragma unroll
        for (int k = 0; k < DATA_F4; ++k)
            cp_async16(edst[k] + (uint32_t)c * EMBUF, esrc[k] + c * DATA_F4);
#pragma unroll
        for (int k = 0; k < TAG_F4; ++k)
            cp_async16(tdst[k] + (uint32_t)c * TGBUF, tsrc[k] + c * TAG_F4);
        cp_commit();
    }

    float w0 = 0.f, w1 = 0.f, w2 = 0.f, w3 = 0.f, w4 = 0.f;
    float clog = 0.f, num = 0.f;
    int prev = 0;

#pragma unroll 1
    for (int c = 0; c < NCHUNK; ++c) {
        const int buf = c & (NBUF - 1);

        cp_wait2();
        __syncwarp();

        // prefetch chunk c+3 (commit ALWAYS -> uniform group count)
        {
            const int pc = c + 3;
            if (pc < NCHUNK) {
                const uint32_t pb = (uint32_t)(pc & (NBUF - 1));
#pragma unroll
                for (int k = 0; k < DATA_F4; ++k)
                    cp_async16(edst[k] + pb * EMBUF, esrc[k] + pc * DATA_F4);
#pragma unroll
                for (int k = 0; k < TAG_F4; ++k)
                    cp_async16(tdst[k] + pb * TGBUF, tsrc[k] + pc * TAG_F4);
            }
            cp_commit();
        }

        // unpack row (conflict-free LDS.128), then hoisted exp burst (independent ILP)
        float e[CHUNK * 5];
        const float4* rowp = &s_em[buf][lane * ROW_F4];
        const float*  emLaneF = reinterpret_cast<const float*>(rowp);  // raw m stays in SMEM
#pragma unroll
        for (int v = 0; v < DATA_F4; ++v) {
            float4 q = rowp[v];
            e[4*v+0] = q.x; e[4*v+1] = q.y; e[4*v+2] = q.z; e[4*v+3] = q.w;
        }
#pragma unroll
        for (int i = 0; i < CHUNK * 5; ++i) e[i] = __expf(e[i]);

        int tg8[8];
        {
            const int4* trow = &s_tg[buf][lane * TROW_F4];
            int4 ta = trow[0], tb = trow[1];
            tg8[0]=ta.x; tg8[1]=ta.y; tg8[2]=ta.z; tg8[3]=ta.w;
            tg8[4]=tb.x; tg8[5]=tb.y; tg8[6]=tb.z; tg8[7]=tb.w;
        }

#define STEP(t) do {                                                                       \
        const int tg = tg8[t];                                                             \
        const float a0 = fmaf(w4,E[20],fmaf(w3,E[15],fmaf(w2,E[10],fmaf(w1,E[5], w0*E[0])))); \
        const float a1 = fmaf(w4,E[21],fmaf(w3,E[16],fmaf(w2,E[11],fmaf(w1,E[6], w0*E[1])))); \
        const float a2 = fmaf(w4,E[22],fmaf(w3,E[17],fmaf(w2,E[12],fmaf(w1,E[7], w0*E[2])))); \
        const float a3 = fmaf(w4,E[23],fmaf(w3,E[18],fmaf(w2,E[13],fmaf(w1,E[8], w0*E[3])))); \
        const float a4 = fmaf(w4,E[24],fmaf(w3,E[19],fmaf(w2,E[14],fmaf(w1,E[9], w0*E[4])))); \
        num += s_T[prev * 5 + tg] + emLaneF[(t)*5 + tg];                                   \
        prev = tg;                                                                         \
        w0 = e[(t)*5+0]*a0; w1 = e[(t)*5+1]*a1; w2 = e[(t)*5+2]*a2;                        \
        w3 = e[(t)*5+3]*a3; w4 = e[(t)*5+4]*a4;                                            \
} while (0)

        if (c == 0) {
            const int tg = tg8[0];
            w0 = ES[0]*e[0]; w1 = ES[1]*e[1]; w2 = ES[2]*e[2];
            w3 = ES[3]*e[3]; w4 = ES[4]*e[4];
            num = s_start[tg] + emLaneF[tg];
            prev = tg;
            STEP(1); STEP(2); STEP(3); STEP(4); STEP(5); STEP(6); STEP(7);
        } else {
            STEP(0); STEP(1); STEP(2); STEP(3);
            STEP(4); STEP(5); STEP(6); STEP(7);
        }
#undef STEP

        // renormalize every 8 steps (growth bound 8*(max|em|+1.8) < 88 -> no overflow)
        const float mx  = fmaxf(fmaxf(w0, w1), fmaxf(fmaxf(w2, w3), w4));
        clog += __logf(mx);
        const float inv = __fdividef(1.0f, mx);
        w0 *= inv; w1 *= inv; w2 *= inv; w3 *= inv; w4 *= inv;
    }

    // ---- epilogue: log partition + gold end transition ----
    const float sden = fmaf(w4, __expf(__ldg(&endT[4])),
                       fmaf(w3, __expf(__ldg(&endT[3])),
                       fmaf(w2, __expf(__ldg(&endT[2])),
                       fmaf(w1, __expf(__ldg(&endT[1])), w0 * __expf(__ldg(&endT[0]))))));
    const float den = clog + __logf(sden);
    num += __ldg(&endT[prev]);

    float val = den - num;

    // ---- warp reduce + last-CTA grid reduction ----
#pragma unroll
    for (int off = 16; off > 0; off >>= 1)
        val += __shfl_down_sync(0xffffffffu, val, off);

    if (lane == 0) {
        g_partial[blockIdx.x] = val;
        __threadfence();
    }
    unsigned tk = 0;
    if (lane == 0) tk = atomicInc(&g_ticket, GRID - 1);   // wraps to 0 -> replay-safe
    tk = __shfl_sync(0xffffffffu, tk, 0);

    if (tk == GRID - 1) {
        __threadfence();
        float s = 0.0f;
#pragma unroll
        for (int i = lane; i < GRID; i += 32) {
            float p;
            asm volatile("ld.global.cv.f32 %0, [%1];" : "=f"(p) : "l"(g_partial + i));
            s += p;
        }
#pragma unroll
        for (int off = 16; off > 0; off >>= 1)
            s += __shfl_down_sync(0xffffffffu, s, off);
        if (lane == 0) out[0] = s * (1.0f / 16384.0f);
    }
}

extern "C" void kernel_launch(void* const* d_in, const int* in_sizes, int n_in,
                              void* d_out, int out_size)
{
    const float* em     = (const float*)d_in[0];
    const float* trans  = (const float*)d_in[1];
    const float* startT = (const float*)d_in[2];
    const float* endT   = (const float*)d_in[3];
    const int*   tags   = (const int*)  d_in[4];
    // d_in[5] = mask (all ones) -> ignored
    float* out = (float*)d_out;

    crf_nll_kernel<<<GRID, TPB>>>(em, trans, startT, endT, tags, out);
}

// round 7
// speedup vs baseline: 1.1905x; 1.0381x over previous
#include <cuda_runtime.h>
#include <cuda_bf16.h>
#include <cstdint>

// CRF mean NLL — bidirectional split: warp0 = forward t=0..255, warp1 = backward t=511..256.
// Z = alpha_255 . beta_255 (5-dot at junction); gold score splits additively with the
// junction transition T[tag255,tag256] added at combine. Doubles warp count to 1024
// (1.73/SMSP) and halves serial length per warp. Same per-step math as R6 body.
// emissions (16384,512,5) f32; transitions (5,5); start/end (5,); tags (16384,512) i32; mask all-ones.

#define TPB         64                   // warp0 fwd, warp1 bwd, same 32 sequences
#define GRID        512
#define CHUNK       8
#define L_SEQ       512
#define NCHUNK_H    32                   // chunks per direction
#define SEQ_PER_CTA 32
#define DATA_F4     10                   // CHUNK*5 floats = 10 float4 per seq per chunk
#define ROW_F4      11                   // padded -> conflict-free LDS.128
#define TAG_F4      2
#define TROW_F4     3
#define NBUF        3
#define EM_ROW_GF4  (L_SEQ * 5 / 4)      // 640 float4 per sequence
#define TG_ROW_GI4  (L_SEQ / 4)          // 128 int4 per sequence

__device__ float        g_partial[GRID];
__device__ unsigned int g_ticket = 0;

__device__ __forceinline__ void cp_async16(uint32_t saddr, const void* gptr) {
    asm volatile("cp.async.cg.shared.global [%0], [%1], 16;\n" :: "r"(saddr), "l"(gptr));
}
__device__ __forceinline__ void cp_commit() {
    asm volatile("cp.async.commit_group;\n");
}
__device__ __forceinline__ void cp_wait1() {
    asm volatile("cp.async.wait_group 1;\n");
}

__global__ __launch_bounds__(TPB)
void crf_nll_kernel(const float* __restrict__ em,
                    const float* __restrict__ trans,
                    const float* __restrict__ startT,
                    const float* __restrict__ endT,
                    const int*   __restrict__ tags,
                    float* __restrict__ out)
{
    __shared__ float4 s_em[2][NBUF][SEQ_PER_CTA * ROW_F4];   // 33792 B
    __shared__ int4   s_tg[2][NBUF][SEQ_PER_CTA * TROW_F4];  //  9216 B
    __shared__ float  s_T[25], s_startv[5], s_endv[5];
    __shared__ float  s_comb[2][SEQ_PER_CTA][8];             //  2048 B

    const int  tid  = threadIdx.x;
    const int  wid  = tid >> 5;          // 0 = forward, 1 = backward
    const int  lane = tid & 31;
    const long seq0 = (long)blockIdx.x * SEQ_PER_CTA;

    if (tid < 25) s_T[tid] = trans[tid];
    if (tid < 5)  { s_startv[tid] = startT[tid]; s_endv[tid] = endT[tid]; }
    __syncthreads();

    float E[25];
#pragma unroll
    for (int i = 0; i < 25; ++i) E[i] = __expf(__ldg(&trans[i]));

    // chunk schedule: fwd cc -> global chunk cc ; bwd cc -> 63-cc
    const int gBase = wid ? (2 * NCHUNK_H - 1) : 0;
    const int gDir  = wid ? -1 : 1;

    // ---- per-lane copy addressing (into this warp's SMEM partition) ----
    const float4* gem = reinterpret_cast<const float4*>(em);
    const int4*   gtg = reinterpret_cast<const int4*>(tags);

    const float4* esrc[DATA_F4];  uint32_t edst[DATA_F4];
#pragma unroll
    for (int k = 0; k < DATA_F4; ++k) {
        int idx = lane + 32 * k;
        int sq  = idx / DATA_F4;
        int v   = idx - sq * DATA_F4;
        esrc[k] = gem + (seq0 + sq) * EM_ROW_GF4 + v;     // + g*DATA_F4 per chunk
        edst[k] = (uint32_t)__cvta_generic_to_shared(&s_em[wid][0][sq * ROW_F4 + v]);
    }
    const int4* tsrc[TAG_F4];  uint32_t tdst[TAG_F4];
#pragma unroll
    for (int k = 0; k < TAG_F4; ++k) {
        int idx = lane + 32 * k;
        int sq  = idx >> 1;
        int v   = idx & 1;
        tsrc[k] = gtg + (seq0 + sq) * TG_ROW_GI4 + v;     // + g*TAG_F4 per chunk
        tdst[k] = (uint32_t)__cvta_generic_to_shared(&s_tg[wid][0][sq * TROW_F4 + v]);
    }

    const uint32_t EMBUF = (uint32_t)(SEQ_PER_CTA * ROW_F4 * 16);
    const uint32_t TGBUF = (uint32_t)(SEQ_PER_CTA * TROW_F4 * 16);

    // ---- prologue: issue chunks for cc=0,1 ----
#pragma unroll
    for (int cc = 0; cc < 2; ++cc) {
        const int g = gBase + gDir * cc;
#pragma unroll
        for (int k = 0; k < DATA_F4; ++k)
            cp_async16(edst[k] + (uint32_t)cc * EMBUF, esrc[k] + g * DATA_F4);
#pragma unroll
        for (int k = 0; k < TAG_F4; ++k)
            cp_async16(tdst[k] + (uint32_t)cc * TGBUF, tsrc[k] + g * TAG_F4);
        cp_commit();
    }

    // per-direction state (only one set used per warp)
    float w0=0.f, w1=0.f, w2=0.f, w3=0.f, w4=0.f;   // fwd alpha or bwd beta
    float clog = 0.f, score = 0.f;
    int   edgeTag = 0;                               // fwd: prev tag; bwd: next tag

    if (wid) {   // backward init: beta = exp(end)
        w0 = __expf(__ldg(&endT[0])); w1 = __expf(__ldg(&endT[1]));
        w2 = __expf(__ldg(&endT[2])); w3 = __expf(__ldg(&endT[3]));
        w4 = __expf(__ldg(&endT[4]));
    }
    float ES[5];
#pragma unroll
    for (int i = 0; i < 5; ++i) ES[i] = __expf(__ldg(&startT[i]));

#pragma unroll 1
    for (int cc = 0; cc < NCHUNK_H; ++cc) {
        const int buf = cc % NBUF;

        cp_wait1();
        __syncwarp();

        // prefetch chunk cc+2 (commit ALWAYS -> uniform group count)
        {
            const int pcc = cc + 2;
            if (pcc < NCHUNK_H) {
                const uint32_t pb = (uint32_t)(pcc % NBUF);
                const int g = gBase + gDir * pcc;
#pragma unroll
                for (int k = 0; k < DATA_F4; ++k)
                    cp_async16(edst[k] + pb * EMBUF, esrc[k] + g * DATA_F4);
#pragma unroll
                for (int k = 0; k < TAG_F4; ++k)
                    cp_async16(tdst[k] + pb * TGBUF, tsrc[k] + g * TAG_F4);
            }
            cp_commit();
        }

        // unpack + hoisted exp burst
        float e[CHUNK * 5];
        const float4* rowp = &s_em[wid][buf][lane * ROW_F4];
        const float*  emLaneF = reinterpret_cast<const float*>(rowp);
#pragma unroll
        for (int v = 0; v < DATA_F4; ++v) {
            float4 q = rowp[v];
            e[4*v+0] = q.x; e[4*v+1] = q.y; e[4*v+2] = q.z; e[4*v+3] = q.w;
        }
#pragma unroll
        for (int i = 0; i < CHUNK * 5; ++i) e[i] = __expf(e[i]);

        int tg8[8];
        {
            const int4* trow = &s_tg[wid][buf][lane * TROW_F4];
            int4 ta = trow[0], tb = trow[1];
            tg8[0]=ta.x; tg8[1]=ta.y; tg8[2]=ta.z; tg8[3]=ta.w;
            tg8[4]=tb.x; tg8[5]=tb.y; tg8[6]=tb.z; tg8[7]=tb.w;
        }

        if (wid == 0) {
            // ---------- FORWARD, steps ascending ----------
#define FSTEP(t) do {                                                                      \
            const int tg = tg8[t];                                                         \
            const float a0 = fmaf(w4,E[20],fmaf(w3,E[15],fmaf(w2,E[10],fmaf(w1,E[5], w0*E[0])))); \
            const float a1 = fmaf(w4,E[21],fmaf(w3,E[16],fmaf(w2,E[11],fmaf(w1,E[6], w0*E[1])))); \
            const float a2 = fmaf(w4,E[22],fmaf(w3,E[17],fmaf(w2,E[12],fmaf(w1,E[7], w0*E[2])))); \
            const float a3 = fmaf(w4,E[23],fmaf(w3,E[18],fmaf(w2,E[13],fmaf(w1,E[8], w0*E[3])))); \
            const float a4 = fmaf(w4,E[24],fmaf(w3,E[19],fmaf(w2,E[14],fmaf(w1,E[9], w0*E[4])))); \
            score += s_T[edgeTag * 5 + tg] + emLaneF[(t)*5 + tg];                          \
            edgeTag = tg;                                                                  \
            w0 = e[(t)*5+0]*a0; w1 = e[(t)*5+1]*a1; w2 = e[(t)*5+2]*a2;                    \
            w3 = e[(t)*5+3]*a3; w4 = e[(t)*5+4]*a4;                                        \
} while (0)
            if (cc == 0) {
                const int tg = tg8[0];
                w0 = ES[0]*e[0]; w1 = ES[1]*e[1]; w2 = ES[2]*e[2];
                w3 = ES[3]*e[3]; w4 = ES[4]*e[4];
                score = s_startv[tg] + emLaneF[tg];
                edgeTag = tg;
                FSTEP(1); FSTEP(2); FSTEP(3); FSTEP(4); FSTEP(5); FSTEP(6); FSTEP(7);
            } else {
                FSTEP(0); FSTEP(1); FSTEP(2); FSTEP(3);
                FSTEP(4); FSTEP(5); FSTEP(6); FSTEP(7);
            }
#undef FSTEP
        } else {
            // ---------- BACKWARD, steps descending ----------
            // beta'_j = sum_k E[j][k] * (e_k * beta_k);  gold pairs (t, t+1): T[tg_t][next]
#define BSTEP(t) do {                                                                      \
            const int tg = tg8[t];                                                         \
            const float u0 = e[(t)*5+0]*w0, u1 = e[(t)*5+1]*w1, u2 = e[(t)*5+2]*w2,        \
                        u3 = e[(t)*5+3]*w3, u4 = e[(t)*5+4]*w4;                            \
            const float b0 = fmaf(u4,E[4],  fmaf(u3,E[3],  fmaf(u2,E[2],  fmaf(u1,E[1],  u0*E[0])))); \
            const float b1 = fmaf(u4,E[9],  fmaf(u3,E[8],  fmaf(u2,E[7],  fmaf(u1,E[6],  u0*E[5])))); \
            const float b2 = fmaf(u4,E[14], fmaf(u3,E[13], fmaf(u2,E[12], fmaf(u1,E[11], u0*E[10])))); \
            const float b3 = fmaf(u4,E[19], fmaf(u3,E[18], fmaf(u2,E[17], fmaf(u1,E[16], u0*E[15])))); \
            const float b4 = fmaf(u4,E[24], fmaf(u3,E[23], fmaf(u2,E[22], fmaf(u1,E[21], u0*E[20])))); \
            score += s_T[tg * 5 + edgeTag] + emLaneF[(t)*5 + tg];                          \
            edgeTag = tg;                                                                  \
            w0 = b0; w1 = b1; w2 = b2; w3 = b3; w4 = b4;                                   \
} while (0)
            if (cc == 0) {
                // first processed step is t=511: end term + emission only (no trans yet)
                const int tg = tg8[7];
                const float u0 = e[35]*w0, u1 = e[36]*w1, u2 = e[37]*w2,
                            u3 = e[38]*w3, u4 = e[39]*w4;
                const float b0 = fmaf(u4,E[4],  fmaf(u3,E[3],  fmaf(u2,E[2],  fmaf(u1,E[1],  u0*E[0]))));
                const float b1 = fmaf(u4,E[9],  fmaf(u3,E[8],  fmaf(u2,E[7],  fmaf(u1,E[6],  u0*E[5]))));
                const float b2 = fmaf(u4,E[14], fmaf(u3,E[13], fmaf(u2,E[12], fmaf(u1,E[11], u0*E[10]))));
                const float b3 = fmaf(u4,E[19], fmaf(u3,E[18], fmaf(u2,E[17], fmaf(u1,E[16], u0*E[15]))));
                const float b4 = fmaf(u4,E[24], fmaf(u3,E[23], fmaf(u2,E[22], fmaf(u1,E[21], u0*E[20]))));
                score = s_endv[tg] + emLaneF[7*5 + tg];
                edgeTag = tg;
                w0 = b0; w1 = b1; w2 = b2; w3 = b3; w4 = b4;
                BSTEP(6); BSTEP(5); BSTEP(4); BSTEP(3); BSTEP(2); BSTEP(1); BSTEP(0);
            } else {
                BSTEP(7); BSTEP(6); BSTEP(5); BSTEP(4);
                BSTEP(3); BSTEP(2); BSTEP(1); BSTEP(0);
            }
#undef BSTEP
        }

        // renormalize every 8 steps
        const float mx  = fmaxf(fmaxf(w0, w1), fmaxf(fmaxf(w2, w3), w4));
        clog += __logf(mx);
        const float inv = __fdividef(1.0f, mx);
        w0 *= inv; w1 *= inv; w2 *= inv; w3 *= inv; w4 *= inv;
    }

    // ---- junction combine via SMEM ----
    {
        float* cb = s_comb[wid][lane];
        cb[0] = w0; cb[1] = w1; cb[2] = w2; cb[3] = w3; cb[4] = w4;
        cb[5] = clog; cb[6] = score; cb[7] = __int_as_float(edgeTag);
    }
    __syncthreads();

    float val = 0.0f;
    if (wid == 0) {
        const float* f = s_comb[0][lane];
        const float* b = s_comb[1][lane];
        const float dot = f[0]*b[0] + f[1]*b[1] + f[2]*b[2] + f[3]*b[3] + f[4]*b[4];
        const int t255 = __float_as_int(f[7]);
        const int t256 = __float_as_int(b[7]);
        const float den = f[5] + b[5] + __logf(dot);
        const float num = f[6] + b[6] + s_T[t255 * 5 + t256];
        val = den - num;

#pragma unroll
        for (int off = 16; off > 0; off >>= 1)
            val += __shfl_down_sync(0xffffffffu, val, off);

        if (lane == 0) {
            g_partial[blockIdx.x] = val;
            __threadfence();
        }
        unsigned tk = 0;
        if (lane == 0) tk = atomicInc(&g_ticket, GRID - 1);   // wraps to 0 -> replay-safe
        tk = __shfl_sync(0xffffffffu, tk, 0);

        if (tk == GRID - 1) {
            __threadfence();
            float s = 0.0f;
#pragma unroll
            for (int i = lane; i < GRID; i += 32) {
                float p;
                asm volatile("ld.global.cv.f32 %0, [%1];" : "=f"(p) : "l"(g_partial + i));
                s += p;
            }
#pragma unroll
            for (int off = 16; off > 0; off >>= 1)
                s += __shfl_down_sync(0xffffffffu, s, off);
            if (lane == 0) out[0] = s * (1.0f / 16384.0f);
        }
    }
}

extern "C" void kernel_launch(void* const* d_in, const int* in_sizes, int n_in,
                              void* d_out, int out_size)
{
    const float* em     = (const float*)d_in[0];
    const float* trans  = (const float*)d_in[1];
    const float* startT = (const float*)d_in[2];
    const float* endT   = (const float*)d_in[3];
    const int*   tags   = (const int*)  d_in[4];
    // d_in[5] = mask (all ones) -> ignored
    float* out = (float*)d_out;

    crf_nll_kernel<<<GRID, TPB>>>(em, trans, startT, endT, tags, out);
}

// round 9
// speedup vs baseline: 1.3232x; 1.1114x over previous
#include <cuda_runtime.h>
#include <cuda_bf16.h>
#include <cstdint>

// CRF mean NLL — bidirectional + 16-step mega-chunks (320B contiguous DRAM granules).
// Theory: all prior configs pinned at ~55% HBM because fetch granule was 160B strided
// 2560B. MEGA=16 doubles... quadruples the contiguous run per (seq,chunk) fetch.
// warp0 = forward t=0..255, warp1 = backward t=511..256; Z = alpha_255 . beta_255.
// emissions (16384,512,5) f32; transitions (5,5); start/end (5,); tags (16384,512) i32; mask=1.

#define TPB         64
#define GRID        512
#define MEGA        16                   // steps per SMEM chunk
#define NMEGA_H     16                   // mega-chunks per direction (256 steps)
#define SEQ_PER_CTA 32
#define E_F4        20                   // MEGA*5/4 float4 per seq per mega-chunk
#define E_ROW       21                   // padded (21 coprime 32 -> conflict-free LDS.128)
#define T_ROW       5                    // 4 int4 tags padded to 5
#define NBUF        2
#define EM_W_F4     (NBUF * SEQ_PER_CTA * E_ROW)   // 1344 f4 per warp
#define TG_W_I4     (NBUF * SEQ_PER_CTA * T_ROW)   // 320 i4 per warp
#define EMBUF_B     (SEQ_PER_CTA * E_ROW * 16)     // 10752 B per buffer
#define TGBUF_B     (SEQ_PER_CTA * T_ROW * 16)     // 2560 B per buffer
#define ESTEP_G     (8 * 2560)           // 8 seq rows in gmem (em)
#define ESTEP_S     (8 * E_ROW * 16)     // 8 seq rows in smem (em)
#define TSTEP_G     (8 * 2048)           // 8 seq rows in gmem (tags)
#define TSTEP_S     (8 * T_ROW * 16)     // 8 seq rows in smem (tags)
#define DYN_BYTES   ((2 * EM_W_F4 + 2 * TG_W_I4) * 16)   // 53248

__device__ float        g_partial[GRID];
__device__ unsigned int g_ticket = 0;

__device__ __forceinline__ void cp_async16(uint32_t saddr, const void* gptr) {
    asm volatile("cp.async.cg.shared.global [%0], [%1], 16;\n" :: "r"(saddr), "l"(gptr));
}
__device__ __forceinline__ void cp_commit() {
    asm volatile("cp.async.commit_group;\n");
}
__device__ __forceinline__ void cp_wait1() {
    asm volatile("cp.async.wait_group 1;\n");
}

__global__ __launch_bounds__(TPB)
void crf_nll_kernel(const float* __restrict__ em,
                    const float* __restrict__ trans,
                    const float* __restrict__ startT,
                    const float* __restrict__ endT,
                    const int*   __restrict__ tags,
                    float* __restrict__ out)
{
    extern __shared__ float4 dyn[];
    __shared__ float s_T[25], s_startv[5], s_endv[5];
    __shared__ float s_comb[2][SEQ_PER_CTA][8];

    const int  tid  = threadIdx.x;
    const int  wid  = tid >> 5;          // 0 = forward, 1 = backward
    const int  lane = tid & 31;
    const long seq0 = (long)blockIdx.x * SEQ_PER_CTA;

    if (tid < 25) s_T[tid] = trans[tid];
    if (tid < 5)  { s_startv[tid] = startT[tid]; s_endv[tid] = endT[tid]; }
    __syncthreads();

    float E[25];
#pragma unroll
    for (int i = 0; i < 25; ++i) E[i] = __expf(__ldg(&trans[i]));

    // per-warp SMEM partitions
    float4* emW = dyn + wid * EM_W_F4;
    int4*   tgW = reinterpret_cast<int4*>(dyn + 2 * EM_W_F4) + wid * TG_W_I4;

    // mega-chunk schedule: fwd mc -> g=mc ; bwd mc -> g=31-mc
    const int gBase = wid ? 31 : 0;
    const int gDir  = wid ? -1 : 1;

    // ---- per-lane copy addressing (k = 5q + r affinity: 5 bases cover 20 copies) ----
    const char* gemB = reinterpret_cast<const char*>(em);
    const char* gtgB = reinterpret_cast<const char*>(tags);

    uint32_t eoff[5], edst[5];
#pragma unroll
    for (int r = 0; r < 5; ++r) {
        int idx = lane + 32 * r;          // 0..159
        int sq  = idx / E_F4;             // 0..7
        int v   = idx - sq * E_F4;
        eoff[r] = (uint32_t)(((seq0 + sq) * 640 + v) * 16);
        edst[r] = (uint32_t)__cvta_generic_to_shared(&emW[sq * E_ROW + v]);
    }
    uint32_t toff, tdst;
    {
        int sq = lane >> 2, v = lane & 3;
        toff = (uint32_t)(((seq0 + sq) * 128 + v) * 16);
        tdst = (uint32_t)__cvta_generic_to_shared(&tgW[sq * T_ROW + v]);
    }

#define ISSUE_MEGA(bufi, g) do {                                                    \
    const uint32_t _eb = (uint32_t)(bufi) * EMBUF_B;                                \
    const uint32_t _tb = (uint32_t)(bufi) * TGBUF_B;                                \
    const uint32_t _ge = (uint32_t)(g) * (MEGA * 5 * 4);                            \
    const uint32_t _gt = (uint32_t)(g) * (MEGA * 4);                                \
    _Pragma("unroll")                                                               \
    for (int r = 0; r < 5; ++r)                                                     \
        _Pragma("unroll")                                                           \
        for (int q = 0; q < 4; ++q)                                                 \
            cp_async16(edst[r] + _eb + q * ESTEP_S,                                 \
                       gemB + (eoff[r] + _ge + q * ESTEP_G));                       \
    _Pragma("unroll")                                                               \
    for (int k = 0; k < 4; ++k)                                                     \
        cp_async16(tdst + _tb + k * TSTEP_S,                                        \
                   gtgB + (toff + _gt + k * TSTEP_G));                              \
} while (0)

    // ---- prologue: issue mega-chunk 0 ----
    ISSUE_MEGA(0, gBase);
    cp_commit();

    float w0=0.f, w1=0.f, w2=0.f, w3=0.f, w4=0.f;
    float clog = 0.f, score = 0.f;
    int   edgeTag = 0;

    if (wid) {   // backward init: beta = exp(end)
        w0 = __expf(__ldg(&endT[0])); w1 = __expf(__ldg(&endT[1]));
        w2 = __expf(__ldg(&endT[2])); w3 = __expf(__ldg(&endT[3]));
        w4 = __expf(__ldg(&endT[4]));
    }
    float ES[5];
#pragma unroll
    for (int i = 0; i < 5; ++i) ES[i] = __expf(__ldg(&startT[i]));

#pragma unroll 1
    for (int mc = 0; mc < NMEGA_H; ++mc) {
        const int buf = mc & 1;

        // issue next mega-chunk first (overlaps the wait); commit ALWAYS
        if (mc + 1 < NMEGA_H) ISSUE_MEGA((mc + 1) & 1, gBase + gDir * (mc + 1));
        cp_commit();

        cp_wait1();
        __syncwarp();

        const float4* laneRow  = emW + buf * (SEQ_PER_CTA * E_ROW) + lane * E_ROW;
        const float*  emLaneF  = reinterpret_cast<const float*>(laneRow);
        const int4*   laneTags = tgW + buf * (SEQ_PER_CTA * T_ROW) + lane * T_ROW;

#pragma unroll
        for (int ss = 0; ss < 2; ++ss) {
            const int sub = wid ? (1 - ss) : ss;     // bwd consumes sub 1 then 0

            float e[40];
            {
                const float4* rowp = laneRow + sub * 10;
#pragma unroll
                for (int v = 0; v < 10; ++v) {
                    float4 q = rowp[v];
                    e[4*v+0] = q.x; e[4*v+1] = q.y; e[4*v+2] = q.z; e[4*v+3] = q.w;
                }
            }
#pragma unroll
            for (int i = 0; i < 40; ++i) e[i] = __expf(e[i]);

            int tg8[8];
            {
                int4 ta = laneTags[sub * 2 + 0], tb = laneTags[sub * 2 + 1];
                tg8[0]=ta.x; tg8[1]=ta.y; tg8[2]=ta.z; tg8[3]=ta.w;
                tg8[4]=tb.x; tg8[5]=tb.y; tg8[6]=tb.z; tg8[7]=tb.w;
            }
            const int gBaseF = sub * 40;   // float offset of this sub-chunk in the lane row

            if (wid == 0) {
#define FSTEP(t) do {                                                                      \
                const int tg = tg8[t];                                                     \
                const float a0 = fmaf(w4,E[20],fmaf(w3,E[15],fmaf(w2,E[10],fmaf(w1,E[5], w0*E[0])))); \
                const float a1 = fmaf(w4,E[21],fmaf(w3,E[16],fmaf(w2,E[11],fmaf(w1,E[6], w0*E[1])))); \
                const float a2 = fmaf(w4,E[22],fmaf(w3,E[17],fmaf(w2,E[12],fmaf(w1,E[7], w0*E[2])))); \
                const float a3 = fmaf(w4,E[23],fmaf(w3,E[18],fmaf(w2,E[13],fmaf(w1,E[8], w0*E[3])))); \
                const float a4 = fmaf(w4,E[24],fmaf(w3,E[19],fmaf(w2,E[14],fmaf(w1,E[9], w0*E[4])))); \
                score += s_T[edgeTag * 5 + tg] + emLaneF[gBaseF + (t)*5 + tg];             \
                edgeTag = tg;                                                              \
                w0 = e[(t)*5+0]*a0; w1 = e[(t)*5+1]*a1; w2 = e[(t)*5+2]*a2;                \
                w3 = e[(t)*5+3]*a3; w4 = e[(t)*5+4]*a4;                                    \
} while (0)
                if (mc == 0 && sub == 0) {
                    const int tg = tg8[0];
                    w0 = ES[0]*e[0]; w1 = ES[1]*e[1]; w2 = ES[2]*e[2];
                    w3 = ES[3]*e[3]; w4 = ES[4]*e[4];
                    score = s_startv[tg] + emLaneF[tg];
                    edgeTag = tg;
                    FSTEP(1); FSTEP(2); FSTEP(3); FSTEP(4); FSTEP(5); FSTEP(6); FSTEP(7);
                } else {
                    FSTEP(0); FSTEP(1); FSTEP(2); FSTEP(3);
                    FSTEP(4); FSTEP(5); FSTEP(6); FSTEP(7);
                }
#undef FSTEP
            } else {
#define BSTEP(t) do {                                                                      \
                const int tg = tg8[t];                                                     \
                const float u0 = e[(t)*5+0]*w0, u1 = e[(t)*5+1]*w1, u2 = e[(t)*5+2]*w2,    \
                            u3 = e[(t)*5+3]*w3, u4 = e[(t)*5+4]*w4;                        \
                const float b0 = fmaf(u4,E[4],  fmaf(u3,E[3],  fmaf(u2,E[2],  fmaf(u1,E[1],  u0*E[0])))); \
                const float b1 = fmaf(u4,E[9],  fmaf(u3,E[8],  fmaf(u2,E[7],  fmaf(u1,E[6],  u0*E[5])))); \
                const float b2 = fmaf(u4,E[14], fmaf(u3,E[13], fmaf(u2,E[12], fmaf(u1,E[11], u0*E[10])))); \
                const float b3 = fmaf(u4,E[19], fmaf(u3,E[18], fmaf(u2,E[17], fmaf(u1,E[16], u0*E[15])))); \
                const float b4 = fmaf(u4,E[24], fmaf(u3,E[23], fmaf(u2,E[22], fmaf(u1,E[21], u0*E[20])))); \
                score += s_T[tg * 5 + edgeTag] + emLaneF[gBaseF + (t)*5 + tg];             \
                edgeTag = tg;                                                              \
                w0 = b0; w1 = b1; w2 = b2; w3 = b3; w4 = b4;                               \
} while (0)
                if (mc == 0 && sub == 1) {
                    // first processed step is t=511: end term + emission only
                    const int tg = tg8[7];
                    const float u0 = e[35]*w0, u1 = e[36]*w1, u2 = e[37]*w2,
                                u3 = e[38]*w3, u4 = e[39]*w4;
                    const float b0 = fmaf(u4,E[4],  fmaf(u3,E[3],  fmaf(u2,E[2],  fmaf(u1,E[1],  u0*E[0]))));
                    const float b1 = fmaf(u4,E[9],  fmaf(u3,E[8],  fmaf(u2,E[7],  fmaf(u1,E[6],  u0*E[5]))));
                    const float b2 = fmaf(u4,E[14], fmaf(u3,E[13], fmaf(u2,E[12], fmaf(u1,E[11], u0*E[10]))));
                    const float b3 = fmaf(u4,E[19], fmaf(u3,E[18], fmaf(u2,E[17], fmaf(u1,E[16], u0*E[15]))));
                    const float b4 = fmaf(u4,E[24], fmaf(u3,E[23], fmaf(u2,E[22], fmaf(u1,E[21], u0*E[20]))));
                    score = s_endv[tg] + emLaneF[gBaseF + 7*5 + tg];
                    edgeTag = tg;
                    w0 = b0; w1 = b1; w2 = b2; w3 = b3; w4 = b4;
                    BSTEP(6); BSTEP(5); BSTEP(4); BSTEP(3); BSTEP(2); BSTEP(1); BSTEP(0);
                } else {
                    BSTEP(7); BSTEP(6); BSTEP(5); BSTEP(4);
                    BSTEP(3); BSTEP(2); BSTEP(1); BSTEP(0);
                }
#undef BSTEP
            }

            // renormalize every 8 steps
            const float mx  = fmaxf(fmaxf(w0, w1), fmaxf(fmaxf(w2, w3), w4));
            clog += __logf(mx);
            const float inv = __fdividef(1.0f, mx);
            w0 *= inv; w1 *= inv; w2 *= inv; w3 *= inv; w4 *= inv;
        }
    }

    // ---- junction combine via SMEM ----
    {
        float* cb = s_comb[wid][lane];
        cb[0] = w0; cb[1] = w1; cb[2] = w2; cb[3] = w3; cb[4] = w4;
        cb[5] = clog; cb[6] = score; cb[7] = __int_as_float(edgeTag);
    }
    __syncthreads();

    if (wid == 0) {
        const float* f = s_comb[0][lane];
        const float* b = s_comb[1][lane];
        const float dot = f[0]*b[0] + f[1]*b[1] + f[2]*b[2] + f[3]*b[3] + f[4]*b[4];
        const int t255 = __float_as_int(f[7]);
        const int t256 = __float_as_int(b[7]);
        const float den = f[5] + b[5] + __logf(dot);
        const float num = f[6] + b[6] + s_T[t255 * 5 + t256];
        float val = den - num;

#pragma unroll
        for (int off = 16; off > 0; off >>= 1)
            val += __shfl_down_sync(0xffffffffu, val, off);

        if (lane == 0) {
            g_partial[blockIdx.x] = val;
            __threadfence();
        }
        unsigned tk = 0;
        if (lane == 0) tk = atomicInc(&g_ticket, GRID - 1);   // wraps to 0 -> replay-safe
        tk = __shfl_sync(0xffffffffu, tk, 0);

        if (tk == GRID - 1) {
            __threadfence();
            float s = 0.0f;
#pragma unroll
            for (int i = lane; i < GRID; i += 32) {
                float p;
                asm volatile("ld.global.cv.f32 %0, [%1];" : "=f"(p) : "l"(g_partial + i));
                s += p;
            }
#pragma unroll
            for (int off = 16; off > 0; off >>= 1)
                s += __shfl_down_sync(0xffffffffu, s, off);
            if (lane == 0) out[0] = s * (1.0f / 16384.0f);
        }
    }
}

extern "C" void kernel_launch(void* const* d_in, const int* in_sizes, int n_in,
                              void* d_out, int out_size)
{
    const float* em     = (const float*)d_in[0];
    const float* trans  = (const float*)d_in[1];
    const float* startT = (const float*)d_in[2];
    const float* endT   = (const float*)d_in[3];
    const int*   tags   = (const int*)  d_in[4];
    // d_in[5] = mask (all ones) -> ignored
    float* out = (float*)d_out;

    cudaFuncSetAttribute(crf_nll_kernel,
                         cudaFuncAttributeMaxDynamicSharedMemorySize, DYN_BYTES);
    crf_nll_kernel<<<GRID, TPB, DYN_BYTES>>>(em, trans, startT, endT, tags, out);
}